// round 3
// baseline (speedup 1.0000x reference)
#include <cuda_runtime.h>
#include <cstdint>

// ---------------------------------------------------------------------------
// Problem constants
// ---------------------------------------------------------------------------
#define NROWS_MAX 100000
#define CONCAT    352     // 128 + 224
#define NODE_DIM  128
#define EQUI_DIM  480
#define OUT_DIM   608

// Scratch (device globals: allocation-free rule)
__device__ float g_cat[(size_t)NROWS_MAX * CONCAT];   // [N,352] normalized concat features
__device__ float g_stats[(size_t)NROWS_MAX * 4];      // per row: m0, r0, r1, r2

// ---------------------------------------------------------------------------
// Helpers
// ---------------------------------------------------------------------------
__device__ __forceinline__ uint32_t f2tf(float x) {
    uint32_t r;
    asm("cvt.rna.tf32.f32 %0, %1;" : "=r"(r) : "f"(x));
    return r;
}

__device__ __forceinline__ void mma_tf32(float* d, const uint32_t* a, uint32_t b0, uint32_t b1) {
    asm volatile(
        "mma.sync.aligned.m16n8k8.row.col.f32.tf32.tf32.f32 "
        "{%0,%1,%2,%3}, {%4,%5,%6,%7}, {%8,%9}, {%0,%1,%2,%3};\n"
        : "+f"(d[0]), "+f"(d[1]), "+f"(d[2]), "+f"(d[3])
        : "r"(a[0]), "r"(a[1]), "r"(a[2]), "r"(a[3]), "r"(b0), "r"(b1));
}

// ---------------------------------------------------------------------------
// Kernel 1: norm / invariants.  One 128-thread block per row.
// cat[row] = [layernorm(node_scalar) (128) | inv0 (128) | inv1 (64) | inv2 (32)]
// stats[row] = {m0, r0, r1, r2}
// ---------------------------------------------------------------------------
__global__ __launch_bounds__(128) void norm_kernel(
    const float* __restrict__ nsc, const float* __restrict__ neq,
    const float* __restrict__ lnw, const float* __restrict__ lnb,
    int N)
{
    int row = blockIdx.x;
    if (row >= N) return;
    int t = threadIdx.x, lane = t & 31, w = t >> 5;
    __shared__ float sh[4][8];

    const float* xs = nsc + (size_t)row * NODE_DIM;
    const float* xe = neq + (size_t)row * EQUI_DIM;

    float x  = xs[t];
    float e0 = xe[t];

    float s1 = 0.f;
    if (t < 64) {
        float a = xe[128 + 3 * t], b = xe[128 + 3 * t + 1], c = xe[128 + 3 * t + 2];
        s1 = a * a + b * b + c * c;
    }
    float s2 = 0.f;
    if (t < 32) {
#pragma unroll
        for (int i = 0; i < 5; i++) { float v = xe[320 + 5 * t + i]; s2 += v * v; }
    }

    // block-reduce 5 values
    float v0 = x, v1 = x * x, v2 = e0, v3 = s1, v4 = s2;
#pragma unroll
    for (int o = 16; o > 0; o >>= 1) {
        v0 += __shfl_xor_sync(~0u, v0, o);
        v1 += __shfl_xor_sync(~0u, v1, o);
        v2 += __shfl_xor_sync(~0u, v2, o);
        v3 += __shfl_xor_sync(~0u, v3, o);
        v4 += __shfl_xor_sync(~0u, v4, o);
    }
    if (lane == 0) { sh[w][0]=v0; sh[w][1]=v1; sh[w][2]=v2; sh[w][3]=v3; sh[w][4]=v4; }
    __syncthreads();
    float sx  = sh[0][0] + sh[1][0] + sh[2][0] + sh[3][0];
    float sxx = sh[0][1] + sh[1][1] + sh[2][1] + sh[3][1];
    float se  = sh[0][2] + sh[1][2] + sh[2][2] + sh[3][2];
    float ss1 = sh[0][3] + sh[1][3] + sh[2][3] + sh[3][3];
    float ss2 = sh[0][4] + sh[1][4] + sh[2][4] + sh[3][4];

    float mu  = sx * (1.f / 128.f);
    float var = sxx * (1.f / 128.f) - mu * mu;
    float rs  = rsqrtf(var + 1e-5f);
    float m0  = se * (1.f / 128.f);
    float c0  = e0 - m0;

    // second reduction: sum of c0^2
    float u = c0 * c0;
#pragma unroll
    for (int o = 16; o > 0; o >>= 1) u += __shfl_xor_sync(~0u, u, o);
    __syncthreads();
    if (lane == 0) sh[w][0] = u;
    __syncthreads();
    float sc2 = sh[0][0] + sh[1][0] + sh[2][0] + sh[3][0];

    float r0 = rsqrtf(sc2 * (1.f / 128.f) + 1e-5f);
    float r1 = rsqrtf(ss1 * (1.f / 64.f) + 1e-5f);
    float r2 = rsqrtf(ss2 * (1.f / 32.f) + 1e-5f);

    float* crow = g_cat + (size_t)row * CONCAT;
    crow[t] = (x - mu) * rs * lnw[t] + lnb[t];
    float eb0 = c0 * r0;
    crow[128 + t] = eb0 * eb0;                                  // /sqrt(1)
    if (t < 64) crow[256 + t] = s1 * r1 * r1 * 0.57735026918962576451f; // /sqrt(3)
    if (t < 32) crow[320 + t] = s2 * r2 * r2 * 0.44721359549995793928f; // /sqrt(5)
    if (t == 0) {
        float4 st = make_float4(m0, r0, r1, r2);
        *(float4*)(g_stats + (size_t)row * 4) = st;
    }
}

// ---------------------------------------------------------------------------
// Kernel 2: fused MLP (GEMM1 -> SiLU -> GEMM2 -> gated epilogue)
// CTA: 128 rows x 352 cols, 512 threads (16 warps, 4M x 4N, warp tile 32x88)
// ---------------------------------------------------------------------------
#define AS_STRIDE 20     // 16 + 4 pad
#define BS_STRIDE 360    // 352 + 8 pad
#define HS_STRIDE 356    // 352 + 4 pad
#define AS_SIZE (128 * AS_STRIDE)       // 2560 floats
#define BS_SIZE (16 * BS_STRIDE)        // 5760
#define HS_SIZE (128 * HS_STRIDE)       // 45568
#define BIAS_SIZE 704
#define STS_SIZE 512
#define SMEM_FLOATS (AS_SIZE + BS_SIZE + HS_SIZE + BIAS_SIZE + STS_SIZE)
#define SMEM_BYTES (SMEM_FLOATS * 4)    // 220416 B

__global__ __launch_bounds__(512, 1) void mlp_kernel(
    const float* __restrict__ W1, const float* __restrict__ b1,
    const float* __restrict__ W2, const float* __restrict__ b2,
    const float* __restrict__ nsc, const float* __restrict__ neq,
    float* __restrict__ out, int N)
{
    extern __shared__ float smem[];
    float* As   = smem;                  // [128][20]
    float* Bs   = As + AS_SIZE;          // [16][360]
    float* Hs   = Bs + BS_SIZE;          // [128][356]
    float* bias = Hs + HS_SIZE;          // [704] : b1 | b2
    float* stS  = bias + BIAS_SIZE;      // [128][4]

    const int tid  = threadIdx.x;
    const int lane = tid & 31;
    const int wid  = tid >> 5;
    const int wm   = wid >> 2;           // 0..3 (M direction)
    const int wn   = wid & 3;            // 0..3 (N direction)
    const int q    = lane >> 2;          // groupID
    const int kq   = lane & 3;           // thread-in-group
    const int rowBase = blockIdx.x * 128;

    // stage biases + per-row stats
    for (int i = tid; i < BIAS_SIZE; i += 512) bias[i] = (i < 352) ? b1[i] : b2[i - 352];
    {
        int r = rowBase + (tid >> 2);
        stS[tid] = (r < N) ? g_stats[(size_t)r * 4 + (tid & 3)] : 0.f;
    }

    float acc[2][11][4];
#pragma unroll
    for (int mt = 0; mt < 2; mt++)
#pragma unroll
        for (int nt = 0; nt < 11; nt++)
#pragma unroll
            for (int e = 0; e < 4; e++) acc[mt][nt][e] = 0.f;

    // =========================== GEMM1: cat @ W1 ===========================
#pragma unroll 1
    for (int kt = 0; kt < 22; ++kt) {
        // load A tile: 128 x 16 (one float4 per thread)
        {
            int r = tid >> 2, seg = tid & 3;
            int gr = rowBase + r;
            float4 v = make_float4(0.f, 0.f, 0.f, 0.f);
            if (gr < N) v = *(const float4*)&g_cat[(size_t)gr * CONCAT + kt * 16 + seg * 4];
            float* dst = &As[r * AS_STRIDE + seg * 4];
            dst[0] = __uint_as_float(f2tf(v.x));
            dst[1] = __uint_as_float(f2tf(v.y));
            dst[2] = __uint_as_float(f2tf(v.z));
            dst[3] = __uint_as_float(f2tf(v.w));
        }
        // load B tile: 16 x 352
        for (int i = tid; i < 16 * 88; i += 512) {
            int k = i / 88, seg = i % 88;
            float4 v = *(const float4*)&W1[(size_t)(kt * 16 + k) * CONCAT + seg * 4];
            float* dst = &Bs[k * BS_STRIDE + seg * 4];
            dst[0] = __uint_as_float(f2tf(v.x));
            dst[1] = __uint_as_float(f2tf(v.y));
            dst[2] = __uint_as_float(f2tf(v.z));
            dst[3] = __uint_as_float(f2tf(v.w));
        }
        __syncthreads();
#pragma unroll
        for (int kk = 0; kk < 16; kk += 8) {
            uint32_t a[2][4];
#pragma unroll
            for (int mt = 0; mt < 2; mt++) {
                int ar = wm * 32 + mt * 16 + q;
                int ac = kk + kq;
                a[mt][0] = __float_as_uint(As[ar * AS_STRIDE + ac]);
                a[mt][1] = __float_as_uint(As[(ar + 8) * AS_STRIDE + ac]);
                a[mt][2] = __float_as_uint(As[ar * AS_STRIDE + ac + 4]);
                a[mt][3] = __float_as_uint(As[(ar + 8) * AS_STRIDE + ac + 4]);
            }
#pragma unroll
            for (int nt = 0; nt < 11; nt++) {
                int bn = wn * 88 + nt * 8 + q;
                int bk = kk + kq;
                uint32_t b0 = __float_as_uint(Bs[bk * BS_STRIDE + bn]);
                uint32_t b1r = __float_as_uint(Bs[(bk + 4) * BS_STRIDE + bn]);
                mma_tf32(acc[0][nt], a[0], b0, b1r);
                mma_tf32(acc[1][nt], a[1], b0, b1r);
            }
        }
        __syncthreads();
    }

    // bias + SiLU -> Hs (tf32-rounded), reset accumulators
#pragma unroll
    for (int mt = 0; mt < 2; mt++)
#pragma unroll
        for (int nt = 0; nt < 11; nt++)
#pragma unroll
            for (int e = 0; e < 4; e++) {
                int r = wm * 32 + mt * 16 + q + ((e >= 2) ? 8 : 0);
                int c = wn * 88 + nt * 8 + 2 * kq + (e & 1);
                float h = acc[mt][nt][e] + bias[c];
                h = __fdividef(h, 1.f + __expf(-h));
                Hs[r * HS_STRIDE + c] = __uint_as_float(f2tf(h));
                acc[mt][nt][e] = 0.f;
            }

    // =========================== GEMM2: H @ W2 =============================
#pragma unroll 1
    for (int kt = 0; kt < 22; ++kt) {
        for (int i = tid; i < 16 * 88; i += 512) {
            int k = i / 88, seg = i % 88;
            float4 v = *(const float4*)&W2[(size_t)(kt * 16 + k) * CONCAT + seg * 4];
            float* dst = &Bs[k * BS_STRIDE + seg * 4];
            dst[0] = __uint_as_float(f2tf(v.x));
            dst[1] = __uint_as_float(f2tf(v.y));
            dst[2] = __uint_as_float(f2tf(v.z));
            dst[3] = __uint_as_float(f2tf(v.w));
        }
        __syncthreads();
#pragma unroll
        for (int kk = 0; kk < 16; kk += 8) {
            uint32_t a[2][4];
            int col = kt * 16 + kk + kq;
#pragma unroll
            for (int mt = 0; mt < 2; mt++) {
                int ar = wm * 32 + mt * 16 + q;
                a[mt][0] = __float_as_uint(Hs[ar * HS_STRIDE + col]);
                a[mt][1] = __float_as_uint(Hs[(ar + 8) * HS_STRIDE + col]);
                a[mt][2] = __float_as_uint(Hs[ar * HS_STRIDE + col + 4]);
                a[mt][3] = __float_as_uint(Hs[(ar + 8) * HS_STRIDE + col + 4]);
            }
#pragma unroll
            for (int nt = 0; nt < 11; nt++) {
                int bn = wn * 88 + nt * 8 + q;
                int bk = kk + kq;
                uint32_t b0 = __float_as_uint(Bs[bk * BS_STRIDE + bn]);
                uint32_t b1r = __float_as_uint(Bs[(bk + 4) * BS_STRIDE + bn]);
                mma_tf32(acc[0][nt], a[0], b0, b1r);
                mma_tf32(acc[1][nt], a[1], b0, b1r);
            }
        }
        __syncthreads();
    }

    // park G = acc + b2 in Hs (raw f32), then coalesced epilogue
#pragma unroll
    for (int mt = 0; mt < 2; mt++)
#pragma unroll
        for (int nt = 0; nt < 11; nt++)
#pragma unroll
            for (int e = 0; e < 4; e++) {
                int r = wm * 32 + mt * 16 + q + ((e >= 2) ? 8 : 0);
                int c = wn * 88 + nt * 8 + 2 * kq + (e & 1);
                Hs[r * HS_STRIDE + c] = acc[mt][nt][e] + bias[352 + c];
            }
    __syncthreads();

    // epilogue: 608 output cols / row = 152 float4 per row
    for (int i = tid; i < 128 * 152; i += 512) {
        int r = i / 152, seg = i % 152;
        int gr = rowBase + r;
        if (gr >= N) continue;
        int oc = seg * 4;
        const float4 st = *(const float4*)&stS[r * 4];   // m0, r0, r1, r2
        const float* G = &Hs[r * HS_STRIDE];
        float4 o;
        if (oc < 128) {
            float4 x = *(const float4*)&nsc[(size_t)gr * NODE_DIM + oc];
            o.x = x.x + G[oc];
            o.y = x.y + G[oc + 1];
            o.z = x.z + G[oc + 2];
            o.w = x.w + G[oc + 3];
        } else if (oc < 256) {
            int gi = oc - 128;
            float4 ne = *(const float4*)&neq[(size_t)gr * EQUI_DIM + gi];
            o.x = ne.x + (ne.x - st.x) * st.y * G[oc];
            o.y = ne.y + (ne.y - st.x) * st.y * G[oc + 1];
            o.z = ne.z + (ne.z - st.x) * st.y * G[oc + 2];
            o.w = ne.w + (ne.w - st.x) * st.y * G[oc + 3];
        } else if (oc < 448) {
            int pos = oc - 256;
            float4 ne = *(const float4*)&neq[(size_t)gr * EQUI_DIM + 128 + pos];
            o.x = ne.x * (1.f + st.z * G[256 + (pos    ) / 3]);
            o.y = ne.y * (1.f + st.z * G[256 + (pos + 1) / 3]);
            o.z = ne.z * (1.f + st.z * G[256 + (pos + 2) / 3]);
            o.w = ne.w * (1.f + st.z * G[256 + (pos + 3) / 3]);
        } else {
            int pos = oc - 448;
            float4 ne = *(const float4*)&neq[(size_t)gr * EQUI_DIM + 320 + pos];
            o.x = ne.x * (1.f + st.w * G[320 + (pos    ) / 5]);
            o.y = ne.y * (1.f + st.w * G[320 + (pos + 1) / 5]);
            o.z = ne.z * (1.f + st.w * G[320 + (pos + 2) / 5]);
            o.w = ne.w * (1.f + st.w * G[320 + (pos + 3) / 5]);
        }
        *(float4*)&out[(size_t)gr * OUT_DIM + oc] = o;
    }
}

// ---------------------------------------------------------------------------
// Launcher
// ---------------------------------------------------------------------------
extern "C" void kernel_launch(void* const* d_in, const int* in_sizes, int n_in,
                              void* d_out, int out_size)
{
    const float* nsc = (const float*)d_in[0];
    const float* neq = (const float*)d_in[1];
    const float* lnw = (const float*)d_in[2];
    const float* lnb = (const float*)d_in[3];
    const float* W1  = (const float*)d_in[4];
    const float* b1  = (const float*)d_in[5];
    const float* W2  = (const float*)d_in[6];
    const float* b2  = (const float*)d_in[7];
    float* out = (float*)d_out;

    int N = in_sizes[0] / NODE_DIM;

    cudaFuncSetAttribute(mlp_kernel, cudaFuncAttributeMaxDynamicSharedMemorySize, SMEM_BYTES);

    norm_kernel<<<N, 128>>>(nsc, neq, lnw, lnb, N);
    int ctas = (N + 127) / 128;
    mlp_kernel<<<ctas, 512, SMEM_BYTES>>>(W1, b1, W2, b2, nsc, neq, out, N);
}

// round 5
// speedup vs baseline: 1.5332x; 1.5332x over previous
#include <cuda_runtime.h>
#include <cstdint>

// ---------------------------------------------------------------------------
// Problem constants
// ---------------------------------------------------------------------------
#define NROWS_MAX 100000
#define CONCAT    352
#define NODE_DIM  128
#define EQUI_DIM  480
#define OUT_DIM   608

// Device-global scratch (allocation-free rule). g_cat padded by 128 rows so the
// last CTA's bulk loads stay in-bounds (pad rows stay zero).
__device__ float g_cat[(size_t)(NROWS_MAX + 128) * CONCAT];
__device__ float g_stats[(size_t)NROWS_MAX * 4];
__device__ float g_w1r[CONCAT * CONCAT];   // W1, tf32-RNA-rounded
__device__ float g_w2r[CONCAT * CONCAT];   // W2, tf32-RNA-rounded

// ---------------------------------------------------------------------------
// PTX helpers (baseline sm_90-era PTX only — NO tcgen05: harness targets sm_103
// without the 'a' feature set)
// ---------------------------------------------------------------------------
__device__ __forceinline__ uint32_t f2tf(float x) {
    uint32_t r;
    asm("cvt.rna.tf32.f32 %0, %1;" : "=r"(r) : "f"(x));
    return r;
}

__device__ __forceinline__ uint32_t smem_to_u32(const void* p) {
    uint32_t a;
    asm("{ .reg .u64 t; cvta.to.shared.u64 t, %1; cvt.u32.u64 %0, t; }" : "=r"(a) : "l"(p));
    return a;
}

__device__ __forceinline__ void mma_tf32(float* d, const uint32_t* a, uint32_t b0, uint32_t b1) {
    asm volatile(
        "mma.sync.aligned.m16n8k8.row.col.f32.tf32.tf32.f32 "
        "{%0,%1,%2,%3}, {%4,%5,%6,%7}, {%8,%9}, {%0,%1,%2,%3};\n"
        : "+f"(d[0]), "+f"(d[1]), "+f"(d[2]), "+f"(d[3])
        : "r"(a[0]), "r"(a[1]), "r"(a[2]), "r"(a[3]), "r"(b0), "r"(b1));
}

#define MBARRIER_INIT(addr, cnt) \
    asm volatile("mbarrier.init.shared.b64 [%0], %1;" :: "r"((uint32_t)(addr)), "r"((uint32_t)(cnt)) : "memory")

#define MBARRIER_EXPECT_TX(addr, bytes) \
    asm volatile("mbarrier.arrive.expect_tx.shared.b64 _, [%0], %1;" \
                 :: "r"((uint32_t)(addr)), "r"((uint32_t)(bytes)) : "memory")

// 1D bulk copy global -> shared, completion via mbarrier (SASS: UBLKCP.S.G)
#define BULK_G2S(dst, src, bytes, mbar) \
    asm volatile("cp.async.bulk.shared::cluster.global.mbarrier::complete_tx::bytes [%0], [%1], %2, [%3];" \
                 :: "r"((uint32_t)(dst)), "l"(src), "r"((uint32_t)(bytes)), "r"((uint32_t)(mbar)) : "memory")

#define MBARRIER_WAIT_PARITY(mbar_smem_addr, phase_parity) do { \
    uint32_t _mbar = (uint32_t)(mbar_smem_addr); \
    uint32_t _parity = (uint32_t)(phase_parity); \
    uint32_t _done; \
    asm volatile( \
        "{\n\t.reg .pred p;\n\t" \
        "mbarrier.try_wait.parity.acquire.cta.shared::cta.b64 p, [%1], %2;\n\t" \
        "selp.b32 %0, 1, 0, p;\n\t}" \
        : "=r"(_done) : "r"(_mbar), "r"(_parity) : "memory"); \
    if (!_done) { \
        asm volatile( \
            "{\n\t.reg .pred P1;\n\t" \
            "WAIT_LOOP_%=:\n\t" \
            "mbarrier.try_wait.parity.acquire.cta.shared::cta.b64 P1, [%0], %1, 0x989680;\n\t" \
            "@P1 bra.uni WAIT_DONE_%=;\n\t" \
            "bra.uni WAIT_LOOP_%=;\n\t" \
            "WAIT_DONE_%=:\n\t}" \
            :: "r"(_mbar), "r"(_parity) : "memory"); \
    } \
} while(0)

// ---------------------------------------------------------------------------
// Kernel 0: elementwise tf32-RNA rounding of weights
// ---------------------------------------------------------------------------
__global__ void round_kernel(const float* __restrict__ W, float* __restrict__ Wr) {
    int i = blockIdx.x * 256 + threadIdx.x;
    if (i < CONCAT * CONCAT) Wr[i] = __uint_as_float(f2tf(W[i]));
}

// ---------------------------------------------------------------------------
// Kernel 1: norm / invariants (identical to the R3 version that passed)
// ---------------------------------------------------------------------------
__global__ __launch_bounds__(128) void norm_kernel(
    const float* __restrict__ nsc, const float* __restrict__ neq,
    const float* __restrict__ lnw, const float* __restrict__ lnb,
    int N)
{
    int row = blockIdx.x;
    if (row >= N) return;
    int t = threadIdx.x, lane = t & 31, w = t >> 5;
    __shared__ float sh[4][8];

    const float* xs = nsc + (size_t)row * NODE_DIM;
    const float* xe = neq + (size_t)row * EQUI_DIM;

    float x  = xs[t];
    float e0 = xe[t];

    float s1 = 0.f;
    if (t < 64) {
        float a = xe[128 + 3 * t], b = xe[128 + 3 * t + 1], c = xe[128 + 3 * t + 2];
        s1 = a * a + b * b + c * c;
    }
    float s2 = 0.f;
    if (t < 32) {
#pragma unroll
        for (int i = 0; i < 5; i++) { float v = xe[320 + 5 * t + i]; s2 += v * v; }
    }

    float v0 = x, v1 = x * x, v2 = e0, v3 = s1, v4 = s2;
#pragma unroll
    for (int o = 16; o > 0; o >>= 1) {
        v0 += __shfl_xor_sync(~0u, v0, o);
        v1 += __shfl_xor_sync(~0u, v1, o);
        v2 += __shfl_xor_sync(~0u, v2, o);
        v3 += __shfl_xor_sync(~0u, v3, o);
        v4 += __shfl_xor_sync(~0u, v4, o);
    }
    if (lane == 0) { sh[w][0]=v0; sh[w][1]=v1; sh[w][2]=v2; sh[w][3]=v3; sh[w][4]=v4; }
    __syncthreads();
    float sx  = sh[0][0] + sh[1][0] + sh[2][0] + sh[3][0];
    float sxx = sh[0][1] + sh[1][1] + sh[2][1] + sh[3][1];
    float se  = sh[0][2] + sh[1][2] + sh[2][2] + sh[3][2];
    float ss1 = sh[0][3] + sh[1][3] + sh[2][3] + sh[3][3];
    float ss2 = sh[0][4] + sh[1][4] + sh[2][4] + sh[3][4];

    float mu  = sx * (1.f / 128.f);
    float var = sxx * (1.f / 128.f) - mu * mu;
    float rs  = rsqrtf(var + 1e-5f);
    float m0  = se * (1.f / 128.f);
    float c0  = e0 - m0;

    float u = c0 * c0;
#pragma unroll
    for (int o = 16; o > 0; o >>= 1) u += __shfl_xor_sync(~0u, u, o);
    __syncthreads();
    if (lane == 0) sh[w][0] = u;
    __syncthreads();
    float sc2 = sh[0][0] + sh[1][0] + sh[2][0] + sh[3][0];

    float r0 = rsqrtf(sc2 * (1.f / 128.f) + 1e-5f);
    float r1 = rsqrtf(ss1 * (1.f / 64.f) + 1e-5f);
    float r2 = rsqrtf(ss2 * (1.f / 32.f) + 1e-5f);

    float* crow = g_cat + (size_t)row * CONCAT;
    crow[t] = __uint_as_float(f2tf((x - mu) * rs * lnw[t] + lnb[t]));
    float eb0 = c0 * r0;
    crow[128 + t] = __uint_as_float(f2tf(eb0 * eb0));
    if (t < 64) crow[256 + t] = __uint_as_float(f2tf(s1 * r1 * r1 * 0.57735026918962576451f));
    if (t < 32) crow[320 + t] = __uint_as_float(f2tf(s2 * r2 * r2 * 0.44721359549995793928f));
    if (t == 0) {
        float4 st = make_float4(m0, r0, r1, r2);
        *(float4*)(g_stats + (size_t)row * 4) = st;
    }
}

// ---------------------------------------------------------------------------
// Kernel 2: fused MLP. 512 threads, 16 warps (4M x 4N), warp tile 32x88.
// A (cat 128x352) resident in smem (stride 356 f); B streamed via a 3-slot
// cp.async.bulk + mbarrier ring (8 k-rows x 352, padded stride 360 f).
//
// smem map (floats unless noted):
//   bias   @0      : 704
//   stats  @704    : 512
//   A/H/G  @1216   : 128*356 = 45568
//   B ring @46784  : 3*8*360 = 8640
//   mbars  @byte 221696 : 3 ring mbars + 1 A mbar (8 B each)
// total 221728 B
// ---------------------------------------------------------------------------
#define SM_BIAS_F  0
#define SM_STATS_F 704
#define SM_A_F     1216
#define SM_B_F     46784
#define SM_MBAR_B  221696
#define SM_MBARA   221720
#define SMEM_TOTAL 221728
#define A_STRIDE   356
#define B_STRIDE   360
#define B_SLOT_F   2880      // 8*360 floats
#define B_SLOT_B   11520     // bytes

__global__ __launch_bounds__(512, 1) void mlp_kernel(
    const float* __restrict__ W1r, const float* __restrict__ W2r,
    const float* __restrict__ b1, const float* __restrict__ b2,
    const float* __restrict__ nsc, const float* __restrict__ neq,
    float* __restrict__ out, int N)
{
    extern __shared__ float smf[];
    uint32_t sb = smem_to_u32(smf);
    const int tid = threadIdx.x, lane = tid & 31, wid = tid >> 5;
    const int wm = wid >> 2, wn = wid & 3;
    const int q = lane >> 2, kq = lane & 3;
    const int rowBase = blockIdx.x * 128;

    if (tid == 0) {
        MBARRIER_INIT(sb + SM_MBAR_B + 0, 1);
        MBARRIER_INIT(sb + SM_MBAR_B + 8, 1);
        MBARRIER_INIT(sb + SM_MBAR_B + 16, 1);
        MBARRIER_INIT(sb + SM_MBARA, 1);
    }
    for (int i = tid; i < 704; i += 512)
        smf[SM_BIAS_F + i] = (i < CONCAT) ? b1[i] : b2[i - CONCAT];
    {
        int si = rowBase * 4 + tid;
        smf[SM_STATS_F + tid] = (si < N * 4) ? g_stats[si] : 0.f;
    }
    __syncthreads();

    // single-producer: stage A (128 rows) + prefetch B tiles 0,1
    if (tid == 0) {
        MBARRIER_EXPECT_TX(sb + SM_MBARA, 128 * 1408);
        const float* asrc = g_cat + (size_t)rowBase * CONCAT;
#pragma unroll 1
        for (int r = 0; r < 128; ++r)
            BULK_G2S(sb + SM_A_F * 4 + r * (A_STRIDE * 4), asrc + r * CONCAT, 1408, sb + SM_MBARA);
#pragma unroll
        for (int t = 0; t < 2; ++t) {
            uint32_t mb = sb + SM_MBAR_B + 8 * t;
            MBARRIER_EXPECT_TX(mb, 11264);
            const float* src = W1r + (size_t)(t * 8) * CONCAT;
            uint32_t dst = sb + SM_B_F * 4 + t * B_SLOT_B;
#pragma unroll
            for (int r = 0; r < 8; ++r)
                BULK_G2S(dst + r * (B_STRIDE * 4), src + r * CONCAT, 1408, mb);
        }
    }

    float acc[2][11][4];
#pragma unroll
    for (int mt = 0; mt < 2; mt++)
#pragma unroll
        for (int nt = 0; nt < 11; nt++)
#pragma unroll
            for (int e = 0; e < 4; e++) acc[mt][nt][e] = 0.f;

    MBARRIER_WAIT_PARITY(sb + SM_MBARA, 0);

    const float* bias = smf + SM_BIAS_F;

    // unified 88-tile loop: tiles 0..43 = GEMM1 (W1), 44..87 = GEMM2 (W2)
#pragma unroll 1
    for (int g = 0; g < 88; ++g) {
        const int slot = g % 3;
        const int par  = (g / 3) & 1;
        MBARRIER_WAIT_PARITY(sb + SM_MBAR_B + 8 * slot, par);
        __syncthreads();   // all warps done with tile g-1; slot (g-1)%3 free

        if (g == 44) {
            // epilogue 1: H = tf32(silu(D1 + b1)) overwrites A in place
#pragma unroll
            for (int mt = 0; mt < 2; mt++) {
                int r0 = wm * 32 + mt * 16 + q;
#pragma unroll
                for (int nt = 0; nt < 11; nt++) {
                    int c = wn * 88 + nt * 8 + 2 * kq;
                    float h0 = acc[mt][nt][0] + bias[c];
                    float h1 = acc[mt][nt][1] + bias[c + 1];
                    float h2 = acc[mt][nt][2] + bias[c];
                    float h3 = acc[mt][nt][3] + bias[c + 1];
                    h0 = __fdividef(h0, 1.f + __expf(-h0));
                    h1 = __fdividef(h1, 1.f + __expf(-h1));
                    h2 = __fdividef(h2, 1.f + __expf(-h2));
                    h3 = __fdividef(h3, 1.f + __expf(-h3));
                    *(float2*)&smf[SM_A_F + r0 * A_STRIDE + c] =
                        make_float2(__uint_as_float(f2tf(h0)), __uint_as_float(f2tf(h1)));
                    *(float2*)&smf[SM_A_F + (r0 + 8) * A_STRIDE + c] =
                        make_float2(__uint_as_float(f2tf(h2)), __uint_as_float(f2tf(h3)));
                    acc[mt][nt][0] = 0.f; acc[mt][nt][1] = 0.f;
                    acc[mt][nt][2] = 0.f; acc[mt][nt][3] = 0.f;
                }
            }
            __syncthreads();
        }

        // producer: prefetch tile g+2 into slot (g+2)%3 (== (g-1)%3, now free)
        if (tid == 0 && g < 86) {
            int t2 = g + 2, s2 = t2 % 3, kc2 = (t2 < 44) ? t2 : t2 - 44;
            uint32_t mb = sb + SM_MBAR_B + 8 * s2;
            MBARRIER_EXPECT_TX(mb, 11264);
            const float* src = ((t2 < 44) ? W1r : W2r) + (size_t)(kc2 * 8) * CONCAT;
            uint32_t dst = sb + SM_B_F * 4 + s2 * B_SLOT_B;
#pragma unroll
            for (int r = 0; r < 8; ++r)
                BULK_G2S(dst + r * (B_STRIDE * 4), src + r * CONCAT, 1408, mb);
        }

        // compute tile g (K = 8)
        const int kc = (g < 44) ? g : g - 44;
        const float* A = smf + SM_A_F;
        const float* B = smf + SM_B_F + slot * B_SLOT_F;
        const int ac = kc * 8 + kq;
        uint32_t a[2][4];
#pragma unroll
        for (int mt = 0; mt < 2; mt++) {
            int ar = wm * 32 + mt * 16 + q;
            a[mt][0] = __float_as_uint(A[ar * A_STRIDE + ac]);
            a[mt][1] = __float_as_uint(A[(ar + 8) * A_STRIDE + ac]);
            a[mt][2] = __float_as_uint(A[ar * A_STRIDE + ac + 4]);
            a[mt][3] = __float_as_uint(A[(ar + 8) * A_STRIDE + ac + 4]);
        }
#pragma unroll
        for (int nt = 0; nt < 11; nt++) {
            int bn = wn * 88 + nt * 8 + q;
            uint32_t b0 = __float_as_uint(B[kq * B_STRIDE + bn]);
            uint32_t b1v = __float_as_uint(B[(kq + 4) * B_STRIDE + bn]);
            mma_tf32(acc[0][nt], a[0], b0, b1v);
            mma_tf32(acc[1][nt], a[1], b0, b1v);
        }
    }

    // epilogue 2: G = D2 + b2 overwrites A in place
    __syncthreads();
#pragma unroll
    for (int mt = 0; mt < 2; mt++) {
        int r0 = wm * 32 + mt * 16 + q;
#pragma unroll
        for (int nt = 0; nt < 11; nt++) {
            int c = wn * 88 + nt * 8 + 2 * kq;
            *(float2*)&smf[SM_A_F + r0 * A_STRIDE + c] =
                make_float2(acc[mt][nt][0] + bias[352 + c], acc[mt][nt][1] + bias[352 + c + 1]);
            *(float2*)&smf[SM_A_F + (r0 + 8) * A_STRIDE + c] =
                make_float2(acc[mt][nt][2] + bias[352 + c], acc[mt][nt][3] + bias[352 + c + 1]);
        }
    }
    __syncthreads();

    // final epilogue: coalesced gated outputs (608 cols = 152 float4 per row)
    const float* stS = smf + SM_STATS_F;
#pragma unroll 1
    for (int i = tid; i < 128 * 152; i += 512) {
        int rr = i / 152, seg = i % 152;
        int gr = rowBase + rr;
        if (gr >= N) continue;
        int oc = seg * 4;
        const float4 st = *(const float4*)&stS[rr * 4];   // m0, r0, r1, r2
        const float* G = smf + SM_A_F + rr * A_STRIDE;
        float4 o;
        if (oc < 128) {
            float4 x = *(const float4*)&nsc[(size_t)gr * NODE_DIM + oc];
            const float4 g4 = *(const float4*)&G[oc];
            o.x = x.x + g4.x; o.y = x.y + g4.y; o.z = x.z + g4.z; o.w = x.w + g4.w;
        } else if (oc < 256) {
            int gi = oc - 128;
            float4 ne = *(const float4*)&neq[(size_t)gr * EQUI_DIM + gi];
            const float4 g4 = *(const float4*)&G[oc];
            o.x = ne.x + (ne.x - st.x) * st.y * g4.x;
            o.y = ne.y + (ne.y - st.x) * st.y * g4.y;
            o.z = ne.z + (ne.z - st.x) * st.y * g4.z;
            o.w = ne.w + (ne.w - st.x) * st.y * g4.w;
        } else if (oc < 448) {
            int pos = oc - 256;
            float4 ne = *(const float4*)&neq[(size_t)gr * EQUI_DIM + 128 + pos];
            o.x = ne.x * (1.f + st.z * G[256 + (pos    ) / 3]);
            o.y = ne.y * (1.f + st.z * G[256 + (pos + 1) / 3]);
            o.z = ne.z * (1.f + st.z * G[256 + (pos + 2) / 3]);
            o.w = ne.w * (1.f + st.z * G[256 + (pos + 3) / 3]);
        } else {
            int pos = oc - 448;
            float4 ne = *(const float4*)&neq[(size_t)gr * EQUI_DIM + 320 + pos];
            o.x = ne.x * (1.f + st.w * G[320 + (pos    ) / 5]);
            o.y = ne.y * (1.f + st.w * G[320 + (pos + 1) / 5]);
            o.z = ne.z * (1.f + st.w * G[320 + (pos + 2) / 5]);
            o.w = ne.w * (1.f + st.w * G[320 + (pos + 3) / 5]);
        }
        *(float4*)&out[(size_t)gr * OUT_DIM + oc] = o;
    }
}

// ---------------------------------------------------------------------------
// Launcher
// ---------------------------------------------------------------------------
extern "C" void kernel_launch(void* const* d_in, const int* in_sizes, int n_in,
                              void* d_out, int out_size)
{
    const float* nsc = (const float*)d_in[0];
    const float* neq = (const float*)d_in[1];
    const float* lnw = (const float*)d_in[2];
    const float* lnb = (const float*)d_in[3];
    const float* W1  = (const float*)d_in[4];
    const float* b1  = (const float*)d_in[5];
    const float* W2  = (const float*)d_in[6];
    const float* b2  = (const float*)d_in[7];
    float* out = (float*)d_out;

    int N = in_sizes[0] / NODE_DIM;

    cudaFuncSetAttribute(mlp_kernel, cudaFuncAttributeMaxDynamicSharedMemorySize, SMEM_TOTAL);

    float *w1r, *w2r;
    cudaGetSymbolAddress((void**)&w1r, g_w1r);
    cudaGetSymbolAddress((void**)&w2r, g_w2r);

    round_kernel<<<(CONCAT * CONCAT + 255) / 256, 256>>>(W1, w1r);
    round_kernel<<<(CONCAT * CONCAT + 255) / 256, 256>>>(W2, w2r);
    norm_kernel<<<N, 128>>>(nsc, neq, lnw, lnb, N);

    int ctas = (N + 127) / 128;
    mlp_kernel<<<ctas, 512, SMEM_TOTAL>>>(w1r, w2r, b1, b2, nsc, neq, out, N);
}

// round 6
// speedup vs baseline: 1.6562x; 1.0803x over previous
#include <cuda_runtime.h>
#include <cstdint>

// ---------------------------------------------------------------------------
// Problem constants
// ---------------------------------------------------------------------------
#define NROWS_MAX 100000
#define CONCAT    352
#define NODE_DIM  128
#define EQUI_DIM  480
#define OUT_DIM   608

// Device-global scratch (allocation-free rule). g_cat padded by 128 rows so the
// last CTA's bulk loads stay in-bounds (pad rows stay zero).
__device__ float g_cat[(size_t)(NROWS_MAX + 128) * CONCAT];
__device__ float g_stats[(size_t)(NROWS_MAX + 128) * 4];
// Packed weights: 44 slots (22 from W1, 22 from W2); slot = 16 k-rows x 360 (padded)
__device__ float g_wpad[44 * 16 * 360];

// ---------------------------------------------------------------------------
// PTX helpers (baseline sm_90-era PTX only — NO tcgen05: harness targets sm_103
// without the 'a' feature set)
// ---------------------------------------------------------------------------
__device__ __forceinline__ uint32_t f2tf(float x) {
    uint32_t r;
    asm("cvt.rna.tf32.f32 %0, %1;" : "=r"(r) : "f"(x));
    return r;
}

__device__ __forceinline__ uint32_t smem_to_u32(const void* p) {
    uint32_t a;
    asm("{ .reg .u64 t; cvta.to.shared.u64 t, %1; cvt.u32.u64 %0, t; }" : "=r"(a) : "l"(p));
    return a;
}

__device__ __forceinline__ void mma_tf32(float* d, const uint32_t* a, uint32_t b0, uint32_t b1) {
    asm volatile(
        "mma.sync.aligned.m16n8k8.row.col.f32.tf32.tf32.f32 "
        "{%0,%1,%2,%3}, {%4,%5,%6,%7}, {%8,%9}, {%0,%1,%2,%3};\n"
        : "+f"(d[0]), "+f"(d[1]), "+f"(d[2]), "+f"(d[3])
        : "r"(a[0]), "r"(a[1]), "r"(a[2]), "r"(a[3]), "r"(b0), "r"(b1));
}

#define MBARRIER_INIT(addr, cnt) \
    asm volatile("mbarrier.init.shared.b64 [%0], %1;" :: "r"((uint32_t)(addr)), "r"((uint32_t)(cnt)) : "memory")

#define MBARRIER_EXPECT_TX(addr, bytes) \
    asm volatile("mbarrier.arrive.expect_tx.shared.b64 _, [%0], %1;" \
                 :: "r"((uint32_t)(addr)), "r"((uint32_t)(bytes)) : "memory")

// 1D bulk copy global -> shared, completion via mbarrier (SASS: UBLKCP.S.G)
#define BULK_G2S(dst, src, bytes, mbar) \
    asm volatile("cp.async.bulk.shared::cluster.global.mbarrier::complete_tx::bytes [%0], [%1], %2, [%3];" \
                 :: "r"((uint32_t)(dst)), "l"(src), "r"((uint32_t)(bytes)), "r"((uint32_t)(mbar)) : "memory")

#define MBARRIER_WAIT_PARITY(mbar_smem_addr, phase_parity) do { \
    uint32_t _mbar = (uint32_t)(mbar_smem_addr); \
    uint32_t _parity = (uint32_t)(phase_parity); \
    uint32_t _done; \
    asm volatile( \
        "{\n\t.reg .pred p;\n\t" \
        "mbarrier.try_wait.parity.acquire.cta.shared::cta.b64 p, [%1], %2;\n\t" \
        "selp.b32 %0, 1, 0, p;\n\t}" \
        : "=r"(_done) : "r"(_mbar), "r"(_parity) : "memory"); \
    if (!_done) { \
        asm volatile( \
            "{\n\t.reg .pred P1;\n\t" \
            "WAIT_LOOP_%=:\n\t" \
            "mbarrier.try_wait.parity.acquire.cta.shared::cta.b64 P1, [%0], %1, 0x989680;\n\t" \
            "@P1 bra.uni WAIT_DONE_%=;\n\t" \
            "bra.uni WAIT_LOOP_%=;\n\t" \
            "WAIT_DONE_%=:\n\t}" \
            :: "r"(_mbar), "r"(_parity) : "memory"); \
    } \
} while(0)

// ---------------------------------------------------------------------------
// Kernel 0: pack W1 / W2 into g_wpad (tf32-RNA-rounded, rows padded to 360)
// slot j (blockIdx.x): j<22 -> W1 rows 16j..16j+15 ; j>=22 -> W2 rows 16(j-22)..
// ---------------------------------------------------------------------------
__global__ void pack_kernel(const float* __restrict__ W1, const float* __restrict__ W2) {
    int j = blockIdx.x;
    const float* src = (j < 22) ? (W1 + (size_t)j * 16 * CONCAT)
                                : (W2 + (size_t)(j - 22) * 16 * CONCAT);
    float* dst = g_wpad + (size_t)j * 16 * 360;
    for (int i = threadIdx.x; i < 16 * CONCAT; i += blockDim.x) {
        int r = i / CONCAT, c = i % CONCAT;
        dst[r * 360 + c] = __uint_as_float(f2tf(src[i]));
    }
}

// ---------------------------------------------------------------------------
// Kernel 1: norm / invariants (identical to the version that passed)
// ---------------------------------------------------------------------------
__global__ __launch_bounds__(128) void norm_kernel(
    const float* __restrict__ nsc, const float* __restrict__ neq,
    const float* __restrict__ lnw, const float* __restrict__ lnb,
    int N)
{
    int row = blockIdx.x;
    if (row >= N) return;
    int t = threadIdx.x, lane = t & 31, w = t >> 5;
    __shared__ float sh[4][8];

    const float* xs = nsc + (size_t)row * NODE_DIM;
    const float* xe = neq + (size_t)row * EQUI_DIM;

    float x  = xs[t];
    float e0 = xe[t];

    float s1 = 0.f;
    if (t < 64) {
        float a = xe[128 + 3 * t], b = xe[128 + 3 * t + 1], c = xe[128 + 3 * t + 2];
        s1 = a * a + b * b + c * c;
    }
    float s2 = 0.f;
    if (t < 32) {
#pragma unroll
        for (int i = 0; i < 5; i++) { float v = xe[320 + 5 * t + i]; s2 += v * v; }
    }

    float v0 = x, v1 = x * x, v2 = e0, v3 = s1, v4 = s2;
#pragma unroll
    for (int o = 16; o > 0; o >>= 1) {
        v0 += __shfl_xor_sync(~0u, v0, o);
        v1 += __shfl_xor_sync(~0u, v1, o);
        v2 += __shfl_xor_sync(~0u, v2, o);
        v3 += __shfl_xor_sync(~0u, v3, o);
        v4 += __shfl_xor_sync(~0u, v4, o);
    }
    if (lane == 0) { sh[w][0]=v0; sh[w][1]=v1; sh[w][2]=v2; sh[w][3]=v3; sh[w][4]=v4; }
    __syncthreads();
    float sx  = sh[0][0] + sh[1][0] + sh[2][0] + sh[3][0];
    float sxx = sh[0][1] + sh[1][1] + sh[2][1] + sh[3][1];
    float se  = sh[0][2] + sh[1][2] + sh[2][2] + sh[3][2];
    float ss1 = sh[0][3] + sh[1][3] + sh[2][3] + sh[3][3];
    float ss2 = sh[0][4] + sh[1][4] + sh[2][4] + sh[3][4];

    float mu  = sx * (1.f / 128.f);
    float var = sxx * (1.f / 128.f) - mu * mu;
    float rs  = rsqrtf(var + 1e-5f);
    float m0  = se * (1.f / 128.f);
    float c0  = e0 - m0;

    float u = c0 * c0;
#pragma unroll
    for (int o = 16; o > 0; o >>= 1) u += __shfl_xor_sync(~0u, u, o);
    __syncthreads();
    if (lane == 0) sh[w][0] = u;
    __syncthreads();
    float sc2 = sh[0][0] + sh[1][0] + sh[2][0] + sh[3][0];

    float r0 = rsqrtf(sc2 * (1.f / 128.f) + 1e-5f);
    float r1 = rsqrtf(ss1 * (1.f / 64.f) + 1e-5f);
    float r2 = rsqrtf(ss2 * (1.f / 32.f) + 1e-5f);

    float* crow = g_cat + (size_t)row * CONCAT;
    crow[t] = __uint_as_float(f2tf((x - mu) * rs * lnw[t] + lnb[t]));
    float eb0 = c0 * r0;
    crow[128 + t] = __uint_as_float(f2tf(eb0 * eb0));
    if (t < 64) crow[256 + t] = __uint_as_float(f2tf(s1 * r1 * r1 * 0.57735026918962576451f));
    if (t < 32) crow[320 + t] = __uint_as_float(f2tf(s2 * r2 * r2 * 0.44721359549995793928f));
    if (t == 0) {
        float4 st = make_float4(m0, r0, r1, r2);
        *(float4*)(g_stats + (size_t)row * 4) = st;
    }
}

// ---------------------------------------------------------------------------
// Kernel 2: fused MLP. 512 threads, 16 warps (4M x 4N), warp tile 32x88.
// A (cat 128x352, stride 356) resident in smem; B streamed in K=16 slots via a
// 2-deep cp.async.bulk ring (one 23040-B contiguous copy per slot from g_wpad).
// 44 iterations total (22 per GEMM); epilogue-1 at iteration 22.
//
// smem map (floats):
//   bias @0        : 704                      (2816 B)
//   A/H/G @704     : 128*356 = 45568          (182272 B) -> ends 46272 f
//   B ring @46272  : 2*16*360 = 11520         (46080 B)  -> ends 57792 f = 231168 B
//   mbars @231168B : ring0, ring1, A  (8 B each)
// total 231200 B  (<= 227 KB opt-in limit 232448)
// ---------------------------------------------------------------------------
#define SM_BIAS_F  0
#define SM_A_F     704
#define SM_B_F     46272
#define SM_MBAR    231168
#define SMEM_TOTAL 231200
#define A_STRIDE   356
#define B_STRIDE   360
#define B_SLOT_F   5760      // 16*360 floats
#define B_SLOT_B   23040     // bytes

__global__ __launch_bounds__(512, 1) void mlp_kernel(
    const float* __restrict__ b1, const float* __restrict__ b2,
    const float* __restrict__ nsc, const float* __restrict__ neq,
    float* __restrict__ out, int N)
{
    extern __shared__ float smf[];
    uint32_t sb = smem_to_u32(smf);
    const int tid = threadIdx.x, lane = tid & 31, wid = tid >> 5;
    const int wm = wid >> 2, wn = wid & 3;
    const int q = lane >> 2, kq = lane & 3;
    const int rowBase = blockIdx.x * 128;

    if (tid == 0) {
        MBARRIER_INIT(sb + SM_MBAR + 0, 1);
        MBARRIER_INIT(sb + SM_MBAR + 8, 1);
        MBARRIER_INIT(sb + SM_MBAR + 16, 1);
    }
    for (int i = tid; i < 704; i += 512)
        smf[SM_BIAS_F + i] = (i < CONCAT) ? b1[i] : b2[i - CONCAT];
    __syncthreads();

    // single-producer: stage A (128 rows) + prefetch B slots 0,1
    if (tid == 0) {
        MBARRIER_EXPECT_TX(sb + SM_MBAR + 16, 128 * 1408);
        const float* asrc = g_cat + (size_t)rowBase * CONCAT;
#pragma unroll 1
        for (int r = 0; r < 128; ++r)
            BULK_G2S(sb + (SM_A_F + r * A_STRIDE) * 4, asrc + r * CONCAT, 1408, sb + SM_MBAR + 16);
#pragma unroll
        for (int s = 0; s < 2; ++s) {
            MBARRIER_EXPECT_TX(sb + SM_MBAR + 8 * s, B_SLOT_B);
            BULK_G2S(sb + (SM_B_F + s * B_SLOT_F) * 4, g_wpad + (size_t)s * B_SLOT_F,
                     B_SLOT_B, sb + SM_MBAR + 8 * s);
        }
    }

    float acc[2][11][4];
#pragma unroll
    for (int mt = 0; mt < 2; mt++)
#pragma unroll
        for (int nt = 0; nt < 11; nt++)
#pragma unroll
            for (int e = 0; e < 4; e++) acc[mt][nt][e] = 0.f;

    MBARRIER_WAIT_PARITY(sb + SM_MBAR + 16, 0);

    const float* bias = smf + SM_BIAS_F;

    // 44 iterations of K=16: 0..21 = GEMM1 (W1), 22..43 = GEMM2 (W2)
#pragma unroll 1
    for (int it = 0; it < 44; ++it) {
        const int slot = it & 1;
        const int par  = (it >> 1) & 1;
        MBARRIER_WAIT_PARITY(sb + SM_MBAR + 8 * slot, par);

        if (it == 22) {
            // epilogue 1: H = tf32(silu(D1 + b1)) overwrites A in place.
            // (end-of-it-21 __syncthreads guarantees all warps finished GEMM1 reads)
#pragma unroll
            for (int mt = 0; mt < 2; mt++) {
                int r0 = wm * 32 + mt * 16 + q;
#pragma unroll
                for (int nt = 0; nt < 11; nt++) {
                    int c = wn * 88 + nt * 8 + 2 * kq;
                    float h0 = acc[mt][nt][0] + bias[c];
                    float h1 = acc[mt][nt][1] + bias[c + 1];
                    float h2 = acc[mt][nt][2] + bias[c];
                    float h3 = acc[mt][nt][3] + bias[c + 1];
                    h0 = __fdividef(h0, 1.f + __expf(-h0));
                    h1 = __fdividef(h1, 1.f + __expf(-h1));
                    h2 = __fdividef(h2, 1.f + __expf(-h2));
                    h3 = __fdividef(h3, 1.f + __expf(-h3));
                    *(float2*)&smf[SM_A_F + r0 * A_STRIDE + c] =
                        make_float2(__uint_as_float(f2tf(h0)), __uint_as_float(f2tf(h1)));
                    *(float2*)&smf[SM_A_F + (r0 + 8) * A_STRIDE + c] =
                        make_float2(__uint_as_float(f2tf(h2)), __uint_as_float(f2tf(h3)));
                    acc[mt][nt][0] = 0.f; acc[mt][nt][1] = 0.f;
                    acc[mt][nt][2] = 0.f; acc[mt][nt][3] = 0.f;
                }
            }
            __syncthreads();
        }

        // compute this K=16 slot (2 k-steps of 8)
        const int kbase = ((it < 22) ? it : it - 22) * 16;
        const float* A = smf + SM_A_F;
        const float* B = smf + SM_B_F + slot * B_SLOT_F;
#pragma unroll
        for (int ks = 0; ks < 2; ++ks) {
            const int ac = kbase + ks * 8 + kq;
            const int bk = ks * 8 + kq;
            uint32_t a[2][4];
#pragma unroll
            for (int mt = 0; mt < 2; mt++) {
                int ar = wm * 32 + mt * 16 + q;
                a[mt][0] = __float_as_uint(A[ar * A_STRIDE + ac]);
                a[mt][1] = __float_as_uint(A[(ar + 8) * A_STRIDE + ac]);
                a[mt][2] = __float_as_uint(A[ar * A_STRIDE + ac + 4]);
                a[mt][3] = __float_as_uint(A[(ar + 8) * A_STRIDE + ac + 4]);
            }
#pragma unroll
            for (int nt = 0; nt < 11; nt++) {
                int bn = wn * 88 + nt * 8 + q;
                uint32_t b0 = __float_as_uint(B[bk * B_STRIDE + bn]);
                uint32_t b1v = __float_as_uint(B[(bk + 4) * B_STRIDE + bn]);
                mma_tf32(acc[0][nt], a[0], b0, b1v);
                mma_tf32(acc[1][nt], a[1], b0, b1v);
            }
        }
        __syncthreads();   // all warps done with slot `it`; safe to refill

        if (tid == 0 && it < 42) {
            int nx = it + 2, s2 = nx & 1;
            MBARRIER_EXPECT_TX(sb + SM_MBAR + 8 * s2, B_SLOT_B);
            BULK_G2S(sb + (SM_B_F + s2 * B_SLOT_F) * 4, g_wpad + (size_t)nx * B_SLOT_F,
                     B_SLOT_B, sb + SM_MBAR + 8 * s2);
        }
    }

    // epilogue 2: G = D2 + b2 overwrites A in place
#pragma unroll
    for (int mt = 0; mt < 2; mt++) {
        int r0 = wm * 32 + mt * 16 + q;
#pragma unroll
        for (int nt = 0; nt < 11; nt++) {
            int c = wn * 88 + nt * 8 + 2 * kq;
            *(float2*)&smf[SM_A_F + r0 * A_STRIDE + c] =
                make_float2(acc[mt][nt][0] + bias[352 + c], acc[mt][nt][1] + bias[352 + c + 1]);
            *(float2*)&smf[SM_A_F + (r0 + 8) * A_STRIDE + c] =
                make_float2(acc[mt][nt][2] + bias[352 + c], acc[mt][nt][3] + bias[352 + c + 1]);
        }
    }
    __syncthreads();

    // final epilogue: coalesced gated outputs (608 cols = 152 float4 per row)
#pragma unroll 1
    for (int i = tid; i < 128 * 152; i += 512) {
        int rr = i / 152, seg = i % 152;
        int gr = rowBase + rr;
        if (gr >= N) continue;
        int oc = seg * 4;
        const float4 st = *(const float4*)&g_stats[(size_t)gr * 4];   // m0, r0, r1, r2
        const float* G = smf + SM_A_F + rr * A_STRIDE;
        float4 o;
        if (oc < 128) {
            float4 x = *(const float4*)&nsc[(size_t)gr * NODE_DIM + oc];
            const float4 g4 = *(const float4*)&G[oc];
            o.x = x.x + g4.x; o.y = x.y + g4.y; o.z = x.z + g4.z; o.w = x.w + g4.w;
        } else if (oc < 256) {
            int gi = oc - 128;
            float4 ne = *(const float4*)&neq[(size_t)gr * EQUI_DIM + gi];
            const float4 g4 = *(const float4*)&G[oc];
            o.x = ne.x + (ne.x - st.x) * st.y * g4.x;
            o.y = ne.y + (ne.y - st.x) * st.y * g4.y;
            o.z = ne.z + (ne.z - st.x) * st.y * g4.z;
            o.w = ne.w + (ne.w - st.x) * st.y * g4.w;
        } else if (oc < 448) {
            int pos = oc - 256;
            float4 ne = *(const float4*)&neq[(size_t)gr * EQUI_DIM + 128 + pos];
            o.x = ne.x * (1.f + st.z * G[256 + (pos    ) / 3]);
            o.y = ne.y * (1.f + st.z * G[256 + (pos + 1) / 3]);
            o.z = ne.z * (1.f + st.z * G[256 + (pos + 2) / 3]);
            o.w = ne.w * (1.f + st.z * G[256 + (pos + 3) / 3]);
        } else {
            int pos = oc - 448;
            float4 ne = *(const float4*)&neq[(size_t)gr * EQUI_DIM + 320 + pos];
            o.x = ne.x * (1.f + st.w * G[320 + (pos    ) / 5]);
            o.y = ne.y * (1.f + st.w * G[320 + (pos + 1) / 5]);
            o.z = ne.z * (1.f + st.w * G[320 + (pos + 2) / 5]);
            o.w = ne.w * (1.f + st.w * G[320 + (pos + 3) / 5]);
        }
        *(float4*)&out[(size_t)gr * OUT_DIM + oc] = o;
    }
}

// ---------------------------------------------------------------------------
// Launcher
// ---------------------------------------------------------------------------
extern "C" void kernel_launch(void* const* d_in, const int* in_sizes, int n_in,
                              void* d_out, int out_size)
{
    const float* nsc = (const float*)d_in[0];
    const float* neq = (const float*)d_in[1];
    const float* lnw = (const float*)d_in[2];
    const float* lnb = (const float*)d_in[3];
    const float* W1  = (const float*)d_in[4];
    const float* b1  = (const float*)d_in[5];
    const float* W2  = (const float*)d_in[6];
    const float* b2  = (const float*)d_in[7];
    float* out = (float*)d_out;

    int N = in_sizes[0] / NODE_DIM;

    cudaFuncSetAttribute(mlp_kernel, cudaFuncAttributeMaxDynamicSharedMemorySize, SMEM_TOTAL);

    pack_kernel<<<44, 256>>>(W1, W2);
    norm_kernel<<<N, 128>>>(nsc, neq, lnw, lnb, N);

    int ctas = (N + 127) / 128;
    mlp_kernel<<<ctas, 512, SMEM_TOTAL>>>(b1, b2, nsc, neq, out, N);
}

// round 9
// speedup vs baseline: 2.4030x; 1.4509x over previous
#include <cuda_runtime.h>
#include <cuda_fp16.h>
#include <cstdint>

// ---------------------------------------------------------------------------
// Problem constants
// ---------------------------------------------------------------------------
#define NROWS_MAX 100000
#define CONCAT    352
#define NODE_DIM  128
#define EQUI_DIM  480
#define OUT_DIM   608

// cat features as fp16, row stride 360 halves (720 B) so one bulk copy stages
// a 64-row tile. Padded by 128 rows for the last CTA (stays zero).
__device__ __half  g_cat_h[(size_t)(NROWS_MAX + 128) * 360];
__device__ float   g_stats[(size_t)(NROWS_MAX + 128) * 4];
// Packed weights: 22 slots (11 W1 + 11 W2); slot = K=32 -> 16 k2-rows x 360
// words; word(k2,n) = half2(W[2k2][n], W[2k2+1][n]).
__device__ uint32_t g_wpad[22 * 16 * 360];

// ---------------------------------------------------------------------------
// PTX helpers (sm_90-era baseline only; tcgen05 rejected by this toolchain)
// ---------------------------------------------------------------------------
__device__ __forceinline__ uint32_t smem_to_u32(const void* p) {
    uint32_t a;
    asm("{ .reg .u64 t; cvta.to.shared.u64 t, %1; cvt.u32.u64 %0, t; }" : "=r"(a) : "l"(p));
    return a;
}

__device__ __forceinline__ void mma_fp16(float* d, const uint32_t* a, uint32_t b0, uint32_t b1) {
    asm volatile(
        "mma.sync.aligned.m16n8k16.row.col.f32.f16.f16.f32 "
        "{%0,%1,%2,%3}, {%4,%5,%6,%7}, {%8,%9}, {%0,%1,%2,%3};\n"
        : "+f"(d[0]), "+f"(d[1]), "+f"(d[2]), "+f"(d[3])
        : "r"(a[0]), "r"(a[1]), "r"(a[2]), "r"(a[3]), "r"(b0), "r"(b1));
}

#define MBARRIER_INIT(addr, cnt) \
    asm volatile("mbarrier.init.shared.b64 [%0], %1;" :: "r"((uint32_t)(addr)), "r"((uint32_t)(cnt)) : "memory")

#define MBARRIER_EXPECT_TX(addr, bytes) \
    asm volatile("mbarrier.arrive.expect_tx.shared.b64 _, [%0], %1;" \
                 :: "r"((uint32_t)(addr)), "r"((uint32_t)(bytes)) : "memory")

#define BULK_G2S(dst, src, bytes, mbar) \
    asm volatile("cp.async.bulk.shared::cluster.global.mbarrier::complete_tx::bytes [%0], [%1], %2, [%3];" \
                 :: "r"((uint32_t)(dst)), "l"(src), "r"((uint32_t)(bytes)), "r"((uint32_t)(mbar)) : "memory")

#define MBARRIER_WAIT_PARITY(mbar_smem_addr, phase_parity) do { \
    uint32_t _mbar = (uint32_t)(mbar_smem_addr); \
    uint32_t _parity = (uint32_t)(phase_parity); \
    uint32_t _done; \
    asm volatile( \
        "{\n\t.reg .pred p;\n\t" \
        "mbarrier.try_wait.parity.acquire.cta.shared::cta.b64 p, [%1], %2;\n\t" \
        "selp.b32 %0, 1, 0, p;\n\t}" \
        : "=r"(_done) : "r"(_mbar), "r"(_parity) : "memory"); \
    if (!_done) { \
        asm volatile( \
            "{\n\t.reg .pred P1;\n\t" \
            "WAIT_LOOP_%=:\n\t" \
            "mbarrier.try_wait.parity.acquire.cta.shared::cta.b64 P1, [%0], %1, 0x989680;\n\t" \
            "@P1 bra.uni WAIT_DONE_%=;\n\t" \
            "bra.uni WAIT_LOOP_%=;\n\t" \
            "WAIT_DONE_%=:\n\t}" \
            :: "r"(_mbar), "r"(_parity) : "memory"); \
    } \
} while(0)

// ---------------------------------------------------------------------------
// Kernel 0: pack W1/W2 -> g_wpad as half2 words, k-pairs, padded stride 360
// slot j: j<11 -> W1 k-rows [32j,32j+32) ; j>=11 -> W2 k-rows [32(j-11),...)
// ---------------------------------------------------------------------------
__global__ void pack_kernel(const float* __restrict__ W1, const float* __restrict__ W2) {
    int j = blockIdx.x;
    const float* src = (j < 11) ? (W1 + (size_t)j * 32 * CONCAT)
                                : (W2 + (size_t)(j - 11) * 32 * CONCAT);
    uint32_t* dst = g_wpad + (size_t)j * 16 * 360;
    for (int i = threadIdx.x; i < 16 * CONCAT; i += blockDim.x) {
        int k2 = i / CONCAT, n = i % CONCAT;
        float lo = src[(size_t)(2 * k2) * CONCAT + n];
        float hi = src[(size_t)(2 * k2 + 1) * CONCAT + n];
        __half2 h = __floats2half2_rn(lo, hi);
        dst[k2 * 360 + n] = *(uint32_t*)&h;
    }
}

// ---------------------------------------------------------------------------
// Kernel 1: norm / invariants. One 128-thread block per row; single reduction
// pass (sc2 = se2 - se^2/128). Writes fp16 cat (stride 360) + f32 stats.
// ---------------------------------------------------------------------------
__global__ __launch_bounds__(128) void norm_kernel(
    const float* __restrict__ nsc, const float* __restrict__ neq,
    const float* __restrict__ lnw, const float* __restrict__ lnb,
    int N)
{
    int row = blockIdx.x;
    if (row >= N) return;
    int t = threadIdx.x, lane = t & 31, w = t >> 5;
    __shared__ float sh[4][8];

    const float* xs = nsc + (size_t)row * NODE_DIM;
    const float* xe = neq + (size_t)row * EQUI_DIM;

    float x  = xs[t];
    float e0 = xe[t];

    float s1 = 0.f;
    if (t < 64) {
        float a = xe[128 + 3 * t], b = xe[128 + 3 * t + 1], c = xe[128 + 3 * t + 2];
        s1 = a * a + b * b + c * c;
    }
    float s2 = 0.f;
    if (t < 32) {
#pragma unroll
        for (int i = 0; i < 5; i++) { float v = xe[320 + 5 * t + i]; s2 += v * v; }
    }

    float v0 = x, v1 = x * x, v2 = e0, v3 = e0 * e0, v4 = s1, v5 = s2;
#pragma unroll
    for (int o = 16; o > 0; o >>= 1) {
        v0 += __shfl_xor_sync(~0u, v0, o);
        v1 += __shfl_xor_sync(~0u, v1, o);
        v2 += __shfl_xor_sync(~0u, v2, o);
        v3 += __shfl_xor_sync(~0u, v3, o);
        v4 += __shfl_xor_sync(~0u, v4, o);
        v5 += __shfl_xor_sync(~0u, v5, o);
    }
    if (lane == 0) { sh[w][0]=v0; sh[w][1]=v1; sh[w][2]=v2; sh[w][3]=v3; sh[w][4]=v4; sh[w][5]=v5; }
    __syncthreads();
    float sx  = sh[0][0] + sh[1][0] + sh[2][0] + sh[3][0];
    float sxx = sh[0][1] + sh[1][1] + sh[2][1] + sh[3][1];
    float se  = sh[0][2] + sh[1][2] + sh[2][2] + sh[3][2];
    float se2 = sh[0][3] + sh[1][3] + sh[2][3] + sh[3][3];
    float ss1 = sh[0][4] + sh[1][4] + sh[2][4] + sh[3][4];
    float ss2 = sh[0][5] + sh[1][5] + sh[2][5] + sh[3][5];

    float mu  = sx * (1.f / 128.f);
    float var = sxx * (1.f / 128.f) - mu * mu;
    float rs  = rsqrtf(var + 1e-5f);
    float m0  = se * (1.f / 128.f);
    float sc2m = se2 * (1.f / 128.f) - m0 * m0;   // mean of (e0-m0)^2

    float r0 = rsqrtf(sc2m + 1e-5f);
    float r1 = rsqrtf(ss1 * (1.f / 64.f) + 1e-5f);
    float r2 = rsqrtf(ss2 * (1.f / 32.f) + 1e-5f);

    __half* crow = g_cat_h + (size_t)row * 360;
    crow[t] = __float2half_rn((x - mu) * rs * lnw[t] + lnb[t]);
    float c0 = e0 - m0;
    crow[128 + t] = __float2half_rn(c0 * c0 * r0 * r0);
    if (t < 64) crow[256 + t] = __float2half_rn(s1 * r1 * r1 * 0.57735026918962576451f);
    if (t < 32) crow[320 + t] = __float2half_rn(s2 * r2 * r2 * 0.44721359549995793928f);
    if (t == 0) {
        float4 st = make_float4(m0, r0, r1, r2);
        *(float4*)(g_stats + (size_t)row * 4) = st;
    }
}

// ---------------------------------------------------------------------------
// Kernel 2: fused MLP, fp16 MMA. 64-row CTAs, 256 threads (8 warps, 2M x 4N,
// warp tile 32x88), 2 CTAs/SM. A (64x352 fp16, word stride 180) resident;
// B streamed as K=32 slots (16 k2-rows x 360 words) via 2-deep bulk ring.
// 22 iterations (11 per GEMM); epilogue-1 at it==11; G (f32) overlays A+ring.
//
// smem bytes:
//   bias  @0      : 704 f32              (2816)
//   A     @2816   : 64*180 words         (46080)  -> 48896
//   ring  @48896  : 2*16*360 words       (46080)  -> 94976
//   G overlay @2816 : 64*356 f32         (91136)  -> 93952  (fits)
//   mbars @94976  : slot0, slot1, A      (24)
// total 95008 B/CTA -> 2 CTAs/SM
// ---------------------------------------------------------------------------
#define SM_A_B     2816
#define SM_RING_B  48896
#define SM_MBAR    94976
#define SMEM_TOTAL 95008
#define B_SLOT_B   23040

__global__ __launch_bounds__(256, 2) void mlp_kernel(
    const float* __restrict__ b1, const float* __restrict__ b2,
    const float* __restrict__ nsc, const float* __restrict__ neq,
    float* __restrict__ out, int N)
{
    extern __shared__ char smc[];
    float* smf = (float*)smc;
    uint32_t sb = smem_to_u32(smc);
    const int tid = threadIdx.x, lane = tid & 31, wid = tid >> 5;
    const int wm = wid >> 2, wn = wid & 3;          // 2 x 4 warp grid
    const int q = lane >> 2, kq = lane & 3;
    const int rowBase = blockIdx.x * 64;

    if (tid == 0) {
        MBARRIER_INIT(sb + SM_MBAR + 0, 1);
        MBARRIER_INIT(sb + SM_MBAR + 8, 1);
        MBARRIER_INIT(sb + SM_MBAR + 16, 1);
    }
    for (int i = tid; i < 704; i += 256)
        smf[i] = (i < CONCAT) ? b1[i] : b2[i - CONCAT];
    __syncthreads();

    // producer: one bulk for A (64 rows x 720 B contiguous), prefetch slots 0,1
    if (tid == 0) {
        MBARRIER_EXPECT_TX(sb + SM_MBAR + 16, 46080);
        BULK_G2S(sb + SM_A_B, g_cat_h + (size_t)rowBase * 360, 46080, sb + SM_MBAR + 16);
#pragma unroll
        for (int s = 0; s < 2; ++s) {
            MBARRIER_EXPECT_TX(sb + SM_MBAR + 8 * s, B_SLOT_B);
            BULK_G2S(sb + SM_RING_B + s * B_SLOT_B, g_wpad + (size_t)s * 5760,
                     B_SLOT_B, sb + SM_MBAR + 8 * s);
        }
    }

    float acc[2][11][4];
#pragma unroll
    for (int mt = 0; mt < 2; mt++)
#pragma unroll
        for (int nt = 0; nt < 11; nt++)
#pragma unroll
            for (int e = 0; e < 4; e++) acc[mt][nt][e] = 0.f;

    MBARRIER_WAIT_PARITY(sb + SM_MBAR + 16, 0);

    uint32_t* Aw = (uint32_t*)(smc + SM_A_B);

    // 22 iterations of K=32: 0..10 = GEMM1 (W1), 11..21 = GEMM2 (W2)
#pragma unroll 1
    for (int it = 0; it < 22; ++it) {
        const int slot = it & 1;
        MBARRIER_WAIT_PARITY(sb + SM_MBAR + 8 * slot, (it >> 1) & 1);

        if (it == 11) {
            // epilogue 1: H = fp16(silu(D1 + b1)) overwrites A in place.
            // (end-of-it-10 __syncthreads guarantees GEMM1 reads finished)
#pragma unroll
            for (int mt = 0; mt < 2; mt++) {
                int r0 = wm * 32 + mt * 16 + q;
#pragma unroll
                for (int nt = 0; nt < 11; nt++) {
                    int c = wn * 88 + nt * 8 + 2 * kq;
                    int c2 = c >> 1;
                    float h0 = acc[mt][nt][0] + smf[c];
                    float h1 = acc[mt][nt][1] + smf[c + 1];
                    float h2 = acc[mt][nt][2] + smf[c];
                    float h3 = acc[mt][nt][3] + smf[c + 1];
                    h0 = __fdividef(h0, 1.f + __expf(-h0));
                    h1 = __fdividef(h1, 1.f + __expf(-h1));
                    h2 = __fdividef(h2, 1.f + __expf(-h2));
                    h3 = __fdividef(h3, 1.f + __expf(-h3));
                    __half2 p01 = __floats2half2_rn(h0, h1);
                    __half2 p23 = __floats2half2_rn(h2, h3);
                    Aw[r0 * 180 + c2] = *(uint32_t*)&p01;
                    Aw[(r0 + 8) * 180 + c2] = *(uint32_t*)&p23;
                    acc[mt][nt][0] = 0.f; acc[mt][nt][1] = 0.f;
                    acc[mt][nt][2] = 0.f; acc[mt][nt][3] = 0.f;
                }
            }
            __syncthreads();
        }

        const int itk = (it < 11) ? it : it - 11;
        const uint32_t* Bw = (const uint32_t*)(smc + SM_RING_B + slot * B_SLOT_B);
#pragma unroll
        for (int ks = 0; ks < 2; ++ks) {
            const int k2 = itk * 16 + ks * 8 + kq;
            uint32_t a[2][4];
#pragma unroll
            for (int mt = 0; mt < 2; mt++) {
                int ar = wm * 32 + mt * 16 + q;
                a[mt][0] = Aw[ar * 180 + k2];
                a[mt][1] = Aw[(ar + 8) * 180 + k2];
                a[mt][2] = Aw[ar * 180 + k2 + 4];
                a[mt][3] = Aw[(ar + 8) * 180 + k2 + 4];
            }
            const int bk = ks * 8 + kq;
#pragma unroll
            for (int nt = 0; nt < 11; nt++) {
                int bn = wn * 88 + nt * 8 + q;
                uint32_t b0 = Bw[bk * 360 + bn];
                uint32_t b1v = Bw[(bk + 4) * 360 + bn];
                mma_fp16(acc[0][nt], a[0], b0, b1v);
                mma_fp16(acc[1][nt], a[1], b0, b1v);
            }
        }
        __syncthreads();   // all warps done with this slot; safe to refill

        if (tid == 0 && it < 20) {
            int nx = it + 2, s2 = nx & 1;
            MBARRIER_EXPECT_TX(sb + SM_MBAR + 8 * s2, B_SLOT_B);
            BULK_G2S(sb + SM_RING_B + s2 * B_SLOT_B, g_wpad + (size_t)nx * 5760,
                     B_SLOT_B, sb + SM_MBAR + 8 * s2);
        }
    }

    // epilogue 2: G = D2 + b2 (f32) overlays A + ring (all reads done)
#pragma unroll
    for (int mt = 0; mt < 2; mt++) {
        int r0 = wm * 32 + mt * 16 + q;
#pragma unroll
        for (int nt = 0; nt < 11; nt++) {
            int c = wn * 88 + nt * 8 + 2 * kq;
            float* G0 = smf + (SM_A_B / 4) + r0 * 356;
            float* G1 = smf + (SM_A_B / 4) + (r0 + 8) * 356;
            *(float2*)&G0[c] = make_float2(acc[mt][nt][0] + smf[352 + c],
                                           acc[mt][nt][1] + smf[352 + c + 1]);
            *(float2*)&G1[c] = make_float2(acc[mt][nt][2] + smf[352 + c],
                                           acc[mt][nt][3] + smf[352 + c + 1]);
        }
    }
    __syncthreads();

    // final epilogue: coalesced gated outputs (608 cols = 152 float4 per row)
#pragma unroll 1
    for (int i = tid; i < 64 * 152; i += 256) {
        int rr = i / 152, seg = i % 152;
        int gr = rowBase + rr;
        if (gr >= N) continue;
        int oc = seg * 4;
        const float4 st = *(const float4*)&g_stats[(size_t)gr * 4];   // m0, r0, r1, r2
        const float* G = smf + (SM_A_B / 4) + rr * 356;
        float4 o;
        if (oc < 128) {
            float4 x = *(const float4*)&nsc[(size_t)gr * NODE_DIM + oc];
            const float4 g4 = *(const float4*)&G[oc];
            o.x = x.x + g4.x; o.y = x.y + g4.y; o.z = x.z + g4.z; o.w = x.w + g4.w;
        } else if (oc < 256) {
            int gi = oc - 128;
            float4 ne = *(const float4*)&neq[(size_t)gr * EQUI_DIM + gi];
            const float4 g4 = *(const float4*)&G[oc];
            o.x = ne.x + (ne.x - st.x) * st.y * g4.x;
            o.y = ne.y + (ne.y - st.x) * st.y * g4.y;
            o.z = ne.z + (ne.z - st.x) * st.y * g4.z;
            o.w = ne.w + (ne.w - st.x) * st.y * g4.w;
        } else if (oc < 448) {
            int pos = oc - 256;
            float4 ne = *(const float4*)&neq[(size_t)gr * EQUI_DIM + 128 + pos];
            o.x = ne.x * (1.f + st.z * G[256 + (pos    ) / 3]);
            o.y = ne.y * (1.f + st.z * G[256 + (pos + 1) / 3]);
            o.z = ne.z * (1.f + st.z * G[256 + (pos + 2) / 3]);
            o.w = ne.w * (1.f + st.z * G[256 + (pos + 3) / 3]);
        } else {
            int pos = oc - 448;
            float4 ne = *(const float4*)&neq[(size_t)gr * EQUI_DIM + 320 + pos];
            o.x = ne.x * (1.f + st.w * G[320 + (pos    ) / 5]);
            o.y = ne.y * (1.f + st.w * G[320 + (pos + 1) / 5]);
            o.z = ne.z * (1.f + st.w * G[320 + (pos + 2) / 5]);
            o.w = ne.w * (1.f + st.w * G[320 + (pos + 3) / 5]);
        }
        *(float4*)&out[(size_t)gr * OUT_DIM + oc] = o;
    }
}

// ---------------------------------------------------------------------------
// Launcher
// ---------------------------------------------------------------------------
extern "C" void kernel_launch(void* const* d_in, const int* in_sizes, int n_in,
                              void* d_out, int out_size)
{
    const float* nsc = (const float*)d_in[0];
    const float* neq = (const float*)d_in[1];
    const float* lnw = (const float*)d_in[2];
    const float* lnb = (const float*)d_in[3];
    const float* W1  = (const float*)d_in[4];
    const float* b1  = (const float*)d_in[5];
    const float* W2  = (const float*)d_in[6];
    const float* b2  = (const float*)d_in[7];
    float* out = (float*)d_out;

    int N = in_sizes[0] / NODE_DIM;

    cudaFuncSetAttribute(mlp_kernel, cudaFuncAttributeMaxDynamicSharedMemorySize, SMEM_TOTAL);

    pack_kernel<<<22, 256>>>(W1, W2);
    norm_kernel<<<N, 128>>>(nsc, neq, lnw, lnb, N);

    int ctas = (N + 63) / 64;
    mlp_kernel<<<ctas, 256, SMEM_TOTAL>>>(b1, b2, nsc, neq, out, N);
}

// round 10
// speedup vs baseline: 3.8549x; 1.6042x over previous
#include <cuda_runtime.h>
#include <cuda_fp16.h>
#include <cstdint>

// ---------------------------------------------------------------------------
// Problem constants
// ---------------------------------------------------------------------------
#define NROWS_MAX 100000
#define CONCAT    352
#define NODE_DIM  128
#define EQUI_DIM  480
#define OUT_DIM   608

// Packed weights: 22 slots (11 W1 + 11 W2); slot = K=32 -> 16 k2-rows x 360
// words; word(k2,n) = half2(W[2k2][n], W[2k2+1][n]).
__device__ uint32_t g_wpad[22 * 16 * 360];

// ---------------------------------------------------------------------------
// PTX helpers (sm_90-era baseline only; tcgen05 rejected by this toolchain)
// ---------------------------------------------------------------------------
__device__ __forceinline__ uint32_t smem_to_u32(const void* p) {
    uint32_t a;
    asm("{ .reg .u64 t; cvta.to.shared.u64 t, %1; cvt.u32.u64 %0, t; }" : "=r"(a) : "l"(p));
    return a;
}

__device__ __forceinline__ void mma_fp16(float* d, const uint32_t* a, uint32_t b0, uint32_t b1) {
    asm volatile(
        "mma.sync.aligned.m16n8k16.row.col.f32.f16.f16.f32 "
        "{%0,%1,%2,%3}, {%4,%5,%6,%7}, {%8,%9}, {%0,%1,%2,%3};\n"
        : "+f"(d[0]), "+f"(d[1]), "+f"(d[2]), "+f"(d[3])
        : "r"(a[0]), "r"(a[1]), "r"(a[2]), "r"(a[3]), "r"(b0), "r"(b1));
}

#define MBARRIER_INIT(addr, cnt) \
    asm volatile("mbarrier.init.shared.b64 [%0], %1;" :: "r"((uint32_t)(addr)), "r"((uint32_t)(cnt)) : "memory")

#define MBARRIER_EXPECT_TX(addr, bytes) \
    asm volatile("mbarrier.arrive.expect_tx.shared.b64 _, [%0], %1;" \
                 :: "r"((uint32_t)(addr)), "r"((uint32_t)(bytes)) : "memory")

#define MBARRIER_ARRIVE(addr) \
    asm volatile("mbarrier.arrive.shared.b64 _, [%0];" :: "r"((uint32_t)(addr)) : "memory")

#define BULK_G2S(dst, src, bytes, mbar) \
    asm volatile("cp.async.bulk.shared::cluster.global.mbarrier::complete_tx::bytes [%0], [%1], %2, [%3];" \
                 :: "r"((uint32_t)(dst)), "l"(src), "r"((uint32_t)(bytes)), "r"((uint32_t)(mbar)) : "memory")

#define MBARRIER_WAIT_PARITY(mbar_smem_addr, phase_parity) do { \
    uint32_t _mbar = (uint32_t)(mbar_smem_addr); \
    uint32_t _parity = (uint32_t)(phase_parity); \
    uint32_t _done; \
    asm volatile( \
        "{\n\t.reg .pred p;\n\t" \
        "mbarrier.try_wait.parity.acquire.cta.shared::cta.b64 p, [%1], %2;\n\t" \
        "selp.b32 %0, 1, 0, p;\n\t}" \
        : "=r"(_done) : "r"(_mbar), "r"(_parity) : "memory"); \
    if (!_done) { \
        asm volatile( \
            "{\n\t.reg .pred P1;\n\t" \
            "WAIT_LOOP_%=:\n\t" \
            "mbarrier.try_wait.parity.acquire.cta.shared::cta.b64 P1, [%0], %1, 0x989680;\n\t" \
            "@P1 bra.uni WAIT_DONE_%=;\n\t" \
            "bra.uni WAIT_LOOP_%=;\n\t" \
            "WAIT_DONE_%=:\n\t}" \
            :: "r"(_mbar), "r"(_parity) : "memory"); \
    } \
} while(0)

// ---------------------------------------------------------------------------
// Kernel 0: pack W1/W2 -> g_wpad as half2 words, k-pairs, padded stride 360
// 176 blocks: block b -> slot j=b/8, part p=b%8 (2 k2-rows per block)
// ---------------------------------------------------------------------------
__global__ void pack_kernel(const float* __restrict__ W1, const float* __restrict__ W2) {
    int b = blockIdx.x;
    int j = b >> 3, p = b & 7;
    const float* src = (j < 11) ? (W1 + (size_t)j * 32 * CONCAT)
                                : (W2 + (size_t)(j - 11) * 32 * CONCAT);
    uint32_t* dst = g_wpad + (size_t)j * 5760;
    for (int i = threadIdx.x; i < 2 * CONCAT; i += 256) {
        int k2 = p * 2 + i / CONCAT, n = i % CONCAT;
        float lo = src[(size_t)(2 * k2) * CONCAT + n];
        float hi = src[(size_t)(2 * k2 + 1) * CONCAT + n];
        __half2 h = __floats2half2_rn(lo, hi);
        dst[k2 * 360 + n] = *(uint32_t*)&h;
    }
}

// ---------------------------------------------------------------------------
// Fused kernel: norm prologue + MLP + gated epilogue.
// 64-row CTAs, 256 threads (8 warps, 2M x 4N, warp tile 32x88), 2 CTAs/SM.
// A (64x352 fp16, word stride 180) built in smem by the norm prologue;
// B streamed as K=32 slots via 2-deep bulk ring with full/free mbarriers.
//
// smem bytes:
//   bias  @0     : 704 f32             (2816)
//   stats @2816  : 64*4 f32            (1024)  -> 3840
//   A     @3840  : 64*180 words        (46080) -> 49920
//   ring  @49920 : 2*16*360 words      (46080) -> 96000
//   mbars @96000 : full0,full1,free0,free1    -> 96032
//   G overlay @3840 : 64*356 f32       (91136) -> 94976 (post-loop, safe)
// total 96032 B/CTA -> 2 CTAs/SM
// ---------------------------------------------------------------------------
#define SM_STATS_F 704
#define SM_A_B     3840
#define SM_RING_B  49920
#define SM_MBAR    96000
#define SMEM_TOTAL 96032
#define B_SLOT_B   23040
#define SM_G_F     960          // float index of G overlay (3840/4)

__global__ __launch_bounds__(256, 2) void mlp_kernel(
    const float* __restrict__ b1, const float* __restrict__ b2,
    const float* __restrict__ lnw, const float* __restrict__ lnb,
    const float* __restrict__ nsc, const float* __restrict__ neq,
    float* __restrict__ out, int N)
{
    extern __shared__ char smc[];
    float* smf = (float*)smc;
    uint32_t sb = smem_to_u32(smc);
    const int tid = threadIdx.x, lane = tid & 31, wid = tid >> 5;
    const int wm = wid >> 2, wn = wid & 3;          // 2 x 4 warp grid
    const int q = lane >> 2, kq = lane & 3;
    const int rowBase = blockIdx.x * 64;

    uint32_t* Aw = (uint32_t*)(smc + SM_A_B);

    if (tid == 0) {
        MBARRIER_INIT(sb + SM_MBAR + 0, 1);   // full0
        MBARRIER_INIT(sb + SM_MBAR + 8, 1);   // full1
        MBARRIER_INIT(sb + SM_MBAR + 16, 8);  // free0 (one arrive per warp)
        MBARRIER_INIT(sb + SM_MBAR + 24, 8);  // free1
    }
    for (int i = tid; i < 704; i += 256)
        smf[i] = (i < CONCAT) ? b1[i] : b2[i - CONCAT];
    __syncthreads();

    // producer: prefetch B slots 0,1
    if (tid == 0) {
#pragma unroll
        for (int s = 0; s < 2; ++s) {
            MBARRIER_EXPECT_TX(sb + SM_MBAR + 8 * s, B_SLOT_B);
            BULK_G2S(sb + SM_RING_B + s * B_SLOT_B, g_wpad + (size_t)s * 5760,
                     B_SLOT_B, sb + SM_MBAR + 8 * s);
        }
    }

    // ---------------- norm prologue: 8 rows per warp ----------------
    {
        const float4 lw4 = *(const float4*)&lnw[lane * 4];
        const float4 lb4 = *(const float4*)&lnb[lane * 4];
#pragma unroll 1
        for (int pass = 0; pass < 8; ++pass) {
            int rr = wid * 8 + pass;
            int gr = rowBase + rr;
            float4 xv = make_float4(0.f, 0.f, 0.f, 0.f);
            float4 ev = make_float4(0.f, 0.f, 0.f, 0.f);
            float a0 = 0.f, a1 = 0.f, a2 = 0.f, a3 = 0.f, a4 = 0.f, a5 = 0.f;
            float q0 = 0.f, q1 = 0.f, q2 = 0.f, q3 = 0.f, q4 = 0.f;
            if (gr < N) {
                const float* xs = nsc + (size_t)gr * NODE_DIM;
                const float* xe = neq + (size_t)gr * EQUI_DIM;
                xv = *(const float4*)&xs[lane * 4];
                ev = *(const float4*)&xe[lane * 4];
                const float* l1p = &xe[128 + 6 * lane];
                a0 = l1p[0]; a1 = l1p[1]; a2 = l1p[2];
                a3 = l1p[3]; a4 = l1p[4]; a5 = l1p[5];
                const float* l2p = &xe[320 + 5 * lane];
                q0 = l2p[0]; q1 = l2p[1]; q2 = l2p[2]; q3 = l2p[3]; q4 = l2p[4];
            }
            float s1a = a0 * a0 + a1 * a1 + a2 * a2;
            float s1b = a3 * a3 + a4 * a4 + a5 * a5;
            float s2  = q0 * q0 + q1 * q1 + q2 * q2 + q3 * q3 + q4 * q4;

            float sx  = xv.x + xv.y + xv.z + xv.w;
            float sxx = xv.x * xv.x + xv.y * xv.y + xv.z * xv.z + xv.w * xv.w;
            float se  = ev.x + ev.y + ev.z + ev.w;
            float se2 = ev.x * ev.x + ev.y * ev.y + ev.z * ev.z + ev.w * ev.w;
            float ssl1 = s1a + s1b;
            float ssl2 = s2;
#pragma unroll
            for (int o = 16; o > 0; o >>= 1) {
                sx   += __shfl_xor_sync(~0u, sx, o);
                sxx  += __shfl_xor_sync(~0u, sxx, o);
                se   += __shfl_xor_sync(~0u, se, o);
                se2  += __shfl_xor_sync(~0u, se2, o);
                ssl1 += __shfl_xor_sync(~0u, ssl1, o);
                ssl2 += __shfl_xor_sync(~0u, ssl2, o);
            }
            float mu  = sx * (1.f / 128.f);
            float var = sxx * (1.f / 128.f) - mu * mu;
            float rs  = rsqrtf(var + 1e-5f);
            float m0  = se * (1.f / 128.f);
            float sc2m = se2 * (1.f / 128.f) - m0 * m0;
            float r0 = rsqrtf(sc2m + 1e-5f);
            float r1 = rsqrtf(ssl1 * (1.f / 64.f) + 1e-5f);
            float r2 = rsqrtf(ssl2 * (1.f / 32.f) + 1e-5f);

            uint32_t* Arow = Aw + rr * 180;
            // scalar LN block: cols 4*lane..+3
            {
                float f0 = (xv.x - mu) * rs * lw4.x + lb4.x;
                float f1 = (xv.y - mu) * rs * lw4.y + lb4.y;
                float f2 = (xv.z - mu) * rs * lw4.z + lb4.z;
                float f3 = (xv.w - mu) * rs * lw4.w + lb4.w;
                __half2 p0 = __floats2half2_rn(f0, f1);
                __half2 p1 = __floats2half2_rn(f2, f3);
                Arow[lane * 2] = *(uint32_t*)&p0;
                Arow[lane * 2 + 1] = *(uint32_t*)&p1;
            }
            // l=0 invariants: cols 128+4*lane..+3 : ((e-m0)*r0)^2
            {
                float g0 = (ev.x - m0) * r0, g1 = (ev.y - m0) * r0;
                float g2 = (ev.z - m0) * r0, g3 = (ev.w - m0) * r0;
                __half2 p0 = __floats2half2_rn(g0 * g0, g1 * g1);
                __half2 p1 = __floats2half2_rn(g2 * g2, g3 * g3);
                Arow[64 + lane * 2] = *(uint32_t*)&p0;
                Arow[64 + lane * 2 + 1] = *(uint32_t*)&p1;
            }
            // l=1 invariants: cols 256+2*lane,+1 : s1*r1^2/sqrt(3)
            {
                float v0 = s1a * r1 * r1 * 0.57735026918962576451f;
                float v1 = s1b * r1 * r1 * 0.57735026918962576451f;
                __half2 p = __floats2half2_rn(v0, v1);
                Arow[128 + lane] = *(uint32_t*)&p;
            }
            // l=2 invariants: col 320+lane : s2*r2^2/sqrt(5)  (pair lanes)
            {
                float v = s2 * r2 * r2 * 0.44721359549995793928f;
                float vhi = __shfl_down_sync(~0u, v, 1);
                if (!(lane & 1)) {
                    __half2 p = __floats2half2_rn(v, vhi);
                    Arow[160 + (lane >> 1)] = *(uint32_t*)&p;
                }
            }
            if (lane == 0)
                *(float4*)&smf[SM_STATS_F + rr * 4] = make_float4(m0, r0, r1, r2);
        }
    }
    __syncthreads();   // A tile + stats complete

    float acc[2][11][4];
#pragma unroll
    for (int mt = 0; mt < 2; mt++)
#pragma unroll
        for (int nt = 0; nt < 11; nt++)
#pragma unroll
            for (int e = 0; e < 4; e++) acc[mt][nt][e] = 0.f;

    // 22 iterations of K=32: 0..10 = GEMM1 (W1), 11..21 = GEMM2 (W2)
#pragma unroll 1
    for (int it = 0; it < 22; ++it) {
        const int slot = it & 1;
        MBARRIER_WAIT_PARITY(sb + SM_MBAR + 8 * slot, (it >> 1) & 1);

        if (it == 11) {
            // epilogue 1: H = fp16(silu(D1 + b1)) overwrites A in place.
            __syncthreads();   // all warps done reading A for GEMM1
#pragma unroll
            for (int mt = 0; mt < 2; mt++) {
                int r0 = wm * 32 + mt * 16 + q;
#pragma unroll
                for (int nt = 0; nt < 11; nt++) {
                    int c = wn * 88 + nt * 8 + 2 * kq;
                    int c2 = c >> 1;
                    float h0 = acc[mt][nt][0] + smf[c];
                    float h1 = acc[mt][nt][1] + smf[c + 1];
                    float h2 = acc[mt][nt][2] + smf[c];
                    float h3 = acc[mt][nt][3] + smf[c + 1];
                    h0 = __fdividef(h0, 1.f + __expf(-h0));
                    h1 = __fdividef(h1, 1.f + __expf(-h1));
                    h2 = __fdividef(h2, 1.f + __expf(-h2));
                    h3 = __fdividef(h3, 1.f + __expf(-h3));
                    __half2 p01 = __floats2half2_rn(h0, h1);
                    __half2 p23 = __floats2half2_rn(h2, h3);
                    Aw[r0 * 180 + c2] = *(uint32_t*)&p01;
                    Aw[(r0 + 8) * 180 + c2] = *(uint32_t*)&p23;
                    acc[mt][nt][0] = 0.f; acc[mt][nt][1] = 0.f;
                    acc[mt][nt][2] = 0.f; acc[mt][nt][3] = 0.f;
                }
            }
            __syncthreads();   // H visible to all warps
        }

        const int itk = (it < 11) ? it : it - 11;
        const uint32_t* Bw = (const uint32_t*)(smc + SM_RING_B + slot * B_SLOT_B);
#pragma unroll
        for (int ks = 0; ks < 2; ++ks) {
            const int k2 = itk * 16 + ks * 8 + kq;
            uint32_t a[2][4];
#pragma unroll
            for (int mt = 0; mt < 2; mt++) {
                int ar = wm * 32 + mt * 16 + q;
                a[mt][0] = Aw[ar * 180 + k2];
                a[mt][1] = Aw[(ar + 8) * 180 + k2];
                a[mt][2] = Aw[ar * 180 + k2 + 4];
                a[mt][3] = Aw[(ar + 8) * 180 + k2 + 4];
            }
            const int bk = ks * 8 + kq;
#pragma unroll
            for (int nt = 0; nt < 11; nt++) {
                int bn = wn * 88 + nt * 8 + q;
                uint32_t b0 = Bw[bk * 360 + bn];
                uint32_t b1v = Bw[(bk + 4) * 360 + bn];
                mma_fp16(acc[0][nt], a[0], b0, b1v);
                mma_fp16(acc[1][nt], a[1], b0, b1v);
            }
        }

        // per-warp release of this slot (replaces block-wide __syncthreads)
        if (lane == 0) MBARRIER_ARRIVE(sb + SM_MBAR + 16 + 8 * slot);

        // producer: refill this slot with tile it+2 once all 8 warps released it
        if (tid == 0 && it < 20) {
            MBARRIER_WAIT_PARITY(sb + SM_MBAR + 16 + 8 * slot, (it >> 1) & 1);
            MBARRIER_EXPECT_TX(sb + SM_MBAR + 8 * slot, B_SLOT_B);
            BULK_G2S(sb + SM_RING_B + slot * B_SLOT_B, g_wpad + (size_t)(it + 2) * 5760,
                     B_SLOT_B, sb + SM_MBAR + 8 * slot);
        }
    }

    // epilogue 2: G = D2 + b2 (f32) overlays A + ring (all reads done)
    __syncthreads();
#pragma unroll
    for (int mt = 0; mt < 2; mt++) {
        int r0 = wm * 32 + mt * 16 + q;
#pragma unroll
        for (int nt = 0; nt < 11; nt++) {
            int c = wn * 88 + nt * 8 + 2 * kq;
            float* G0 = smf + SM_G_F + r0 * 356;
            float* G1 = smf + SM_G_F + (r0 + 8) * 356;
            *(float2*)&G0[c] = make_float2(acc[mt][nt][0] + smf[352 + c],
                                           acc[mt][nt][1] + smf[352 + c + 1]);
            *(float2*)&G1[c] = make_float2(acc[mt][nt][2] + smf[352 + c],
                                           acc[mt][nt][3] + smf[352 + c + 1]);
        }
    }
    __syncthreads();

    // final epilogue: coalesced gated outputs (608 cols = 152 float4 per row)
#pragma unroll 1
    for (int i = tid; i < 64 * 152; i += 256) {
        int rr = i / 152, seg = i % 152;
        int gr = rowBase + rr;
        if (gr >= N) continue;
        int oc = seg * 4;
        const float4 st = *(const float4*)&smf[SM_STATS_F + rr * 4]; // m0,r0,r1,r2
        const float* G = smf + SM_G_F + rr * 356;
        float4 o;
        if (oc < 128) {
            float4 x = *(const float4*)&nsc[(size_t)gr * NODE_DIM + oc];
            const float4 g4 = *(const float4*)&G[oc];
            o.x = x.x + g4.x; o.y = x.y + g4.y; o.z = x.z + g4.z; o.w = x.w + g4.w;
        } else if (oc < 256) {
            int gi = oc - 128;
            float4 ne = *(const float4*)&neq[(size_t)gr * EQUI_DIM + gi];
            const float4 g4 = *(const float4*)&G[oc];
            o.x = ne.x + (ne.x - st.x) * st.y * g4.x;
            o.y = ne.y + (ne.y - st.x) * st.y * g4.y;
            o.z = ne.z + (ne.z - st.x) * st.y * g4.z;
            o.w = ne.w + (ne.w - st.x) * st.y * g4.w;
        } else if (oc < 448) {
            int pos = oc - 256;
            float4 ne = *(const float4*)&neq[(size_t)gr * EQUI_DIM + 128 + pos];
            o.x = ne.x * (1.f + st.z * G[256 + (pos    ) / 3]);
            o.y = ne.y * (1.f + st.z * G[256 + (pos + 1) / 3]);
            o.z = ne.z * (1.f + st.z * G[256 + (pos + 2) / 3]);
            o.w = ne.w * (1.f + st.z * G[256 + (pos + 3) / 3]);
        } else {
            int pos = oc - 448;
            float4 ne = *(const float4*)&neq[(size_t)gr * EQUI_DIM + 320 + pos];
            o.x = ne.x * (1.f + st.w * G[320 + (pos    ) / 5]);
            o.y = ne.y * (1.f + st.w * G[320 + (pos + 1) / 5]);
            o.z = ne.z * (1.f + st.w * G[320 + (pos + 2) / 5]);
            o.w = ne.w * (1.f + st.w * G[320 + (pos + 3) / 5]);
        }
        *(float4*)&out[(size_t)gr * OUT_DIM + oc] = o;
    }
}

// ---------------------------------------------------------------------------
// Launcher
// ---------------------------------------------------------------------------
extern "C" void kernel_launch(void* const* d_in, const int* in_sizes, int n_in,
                              void* d_out, int out_size)
{
    const float* nsc = (const float*)d_in[0];
    const float* neq = (const float*)d_in[1];
    const float* lnw = (const float*)d_in[2];
    const float* lnb = (const float*)d_in[3];
    const float* W1  = (const float*)d_in[4];
    const float* b1  = (const float*)d_in[5];
    const float* W2  = (const float*)d_in[6];
    const float* b2  = (const float*)d_in[7];
    float* out = (float*)d_out;

    int N = in_sizes[0] / NODE_DIM;

    cudaFuncSetAttribute(mlp_kernel, cudaFuncAttributeMaxDynamicSharedMemorySize, SMEM_TOTAL);

    pack_kernel<<<176, 256>>>(W1, W2);

    int ctas = (N + 63) / 64;
    mlp_kernel<<<ctas, 256, SMEM_TOTAL>>>(b1, b2, lnw, lnb, nsc, neq, out, N);
}